// round 5
// baseline (speedup 1.0000x reference)
#include <cuda_runtime.h>
#include <math.h>
#include <math_constants.h>
#include <cstdint>

// Problem shape (fixed by the reference)
constexpr int B_ = 8;
constexpr int T_ = 2048;
constexpr int E_ = 1024;
constexpr int H_ = 64;
constexpr int MT = B_ * T_;   // 16384 rows

// Scratch for projected q,k,v — device globals (no allocs allowed)
__device__ float g_q[MT * H_];
__device__ float g_k[MT * H_];
__device__ float g_v[MT * H_];

// ===========================================================================
// Baseline-PTX tensor helpers (mma.sync tf32 — assembles at compute_103)
// ===========================================================================
__device__ __forceinline__ float tf32r(float v) {
    uint32_t u;
    asm("cvt.rna.tf32.f32 %0, %1;" : "=r"(u) : "f"(v));
    return __uint_as_float(u);
}
// hi = rna(v); lo = rna(v - hi).  hi*hi + hi*lo + lo*hi ~ fp32 (err ~2^-24)
__device__ __forceinline__ void split4(const float4& v, float4& h, float4& l) {
    h.x = tf32r(v.x); l.x = tf32r(v.x - h.x);
    h.y = tf32r(v.y); l.y = tf32r(v.y - h.y);
    h.z = tf32r(v.z); l.z = tf32r(v.z - h.z);
    h.w = tf32r(v.w); l.w = tf32r(v.w - h.w);
}
__device__ __forceinline__ float4 rnd4(const float4& v) {
    return make_float4(tf32r(v.x), tf32r(v.y), tf32r(v.z), tf32r(v.w));
}
// D += A(16x8) * B(8x8): m16n8k8 tf32, fp32 accumulate
__device__ __forceinline__ void mma8(float* c,
                                     uint32_t a0, uint32_t a1, uint32_t a2, uint32_t a3,
                                     uint32_t b0, uint32_t b1) {
    asm volatile(
        "mma.sync.aligned.m16n8k8.row.col.f32.tf32.tf32.f32 "
        "{%0,%1,%2,%3}, {%4,%5,%6,%7}, {%8,%9}, {%0,%1,%2,%3};"
        : "+f"(c[0]), "+f"(c[1]), "+f"(c[2]), "+f"(c[3])
        : "r"(a0), "r"(a1), "r"(a2), "r"(a3), "r"(b0), "r"(b1));
}
__device__ __forceinline__ uint32_t fu(float v) { return __float_as_uint(v); }

// ===========================================================================
// Kernel 1: QKV projection, tf32 mma.sync.
// out[m][h] = sum_e x[m][e] * W[h][e].  CTA: 128 rows x 64 cols, 8 warps,
// warp = 16 rows x 64 cols.  BK=32 chunks, reg prefetch of next chunk.
// THREE_TERM=true for Wq/Wk (grid.y 0,1), false for Wv (single tf32).
// QPAD=36 (≡4 mod 32): fragment LDS banks (4g + c + 8kt) — conflict-free.
// ===========================================================================
constexpr int QPAD = 36;

template <bool THREE_TERM>
__global__ __launch_bounds__(256, 2) void qkv_mma_kernel(
    const float* __restrict__ x,
    const float* __restrict__ Wq,
    const float* __restrict__ Wk,
    const float* __restrict__ Wv)
{
    extern __shared__ float sq[];
    float* Xhi = sq;                                       // [128][36]
    float* Xlo = THREE_TERM ? Xhi + 128 * QPAD : nullptr;
    float* Bhi = THREE_TERM ? Xlo + 128 * QPAD : Xhi + 128 * QPAD;  // [64][36]
    float* Blo = THREE_TERM ? Bhi + 64 * QPAD : nullptr;

    const float* W = THREE_TERM ? (blockIdx.y == 0 ? Wq : Wk) : Wv;
    float* outp    = THREE_TERM ? (blockIdx.y == 0 ? g_q : g_k) : g_v;

    const int m0   = blockIdx.x * 128;
    const int tid  = threadIdx.x;
    const int warp = tid >> 5, lane = tid & 31;
    const int g = lane >> 2, c = lane & 3;
    const int wb = warp * 16;

    float acc[8][4];
#pragma unroll
    for (int nt = 0; nt < 8; nt++)
#pragma unroll
        for (int i = 0; i < 4; i++) acc[nt][i] = 0.f;

    float4 xr[4], wr[2];
    auto ldg = [&](int k0) {
#pragma unroll
        for (int i = 0; i < 4; i++) {
            int idx = tid + i * 256, r = idx >> 3, c4 = (idx & 7) * 4;
            xr[i] = *reinterpret_cast<const float4*>(&x[(size_t)(m0 + r) * E_ + k0 + c4]);
        }
#pragma unroll
        for (int i = 0; i < 2; i++) {
            int idx = tid + i * 256, r = idx >> 3, c4 = (idx & 7) * 4;
            wr[i] = *reinterpret_cast<const float4*>(&W[(size_t)r * E_ + k0 + c4]);
        }
    };
    auto sts = [&]() {
#pragma unroll
        for (int i = 0; i < 4; i++) {
            int idx = tid + i * 256, r = idx >> 3, c4 = (idx & 7) * 4;
            if (THREE_TERM) {
                float4 h, l; split4(xr[i], h, l);
                *reinterpret_cast<float4*>(&Xhi[r * QPAD + c4]) = h;
                *reinterpret_cast<float4*>(&Xlo[r * QPAD + c4]) = l;
            } else {
                *reinterpret_cast<float4*>(&Xhi[r * QPAD + c4]) = rnd4(xr[i]);
            }
        }
#pragma unroll
        for (int i = 0; i < 2; i++) {
            int idx = tid + i * 256, r = idx >> 3, c4 = (idx & 7) * 4;
            if (THREE_TERM) {
                float4 h, l; split4(wr[i], h, l);
                *reinterpret_cast<float4*>(&Bhi[r * QPAD + c4]) = h;
                *reinterpret_cast<float4*>(&Blo[r * QPAD + c4]) = l;
            } else {
                *reinterpret_cast<float4*>(&Bhi[r * QPAD + c4]) = rnd4(wr[i]);
            }
        }
    };

    ldg(0); sts(); __syncthreads();

    for (int ch = 0; ch < 32; ch++) {
        if (ch < 31) ldg((ch + 1) * 32);   // prefetch next chunk into regs
#pragma unroll
        for (int kt = 0; kt < 4; kt++) {
            const int ka = kt * 8 + c;
            const int ra = (wb + g) * QPAD, rb = (wb + g + 8) * QPAD;
            uint32_t ah0 = fu(Xhi[ra + ka]),     ah1 = fu(Xhi[rb + ka]);
            uint32_t ah2 = fu(Xhi[ra + ka + 4]), ah3 = fu(Xhi[rb + ka + 4]);
            uint32_t al0 = 0, al1 = 0, al2 = 0, al3 = 0;
            if (THREE_TERM) {
                al0 = fu(Xlo[ra + ka]);     al1 = fu(Xlo[rb + ka]);
                al2 = fu(Xlo[ra + ka + 4]); al3 = fu(Xlo[rb + ka + 4]);
            }
#pragma unroll
            for (int nt = 0; nt < 8; nt++) {
                const int br = (nt * 8 + g) * QPAD + ka;
                uint32_t bh0 = fu(Bhi[br]), bh1 = fu(Bhi[br + 4]);
                mma8(acc[nt], ah0, ah1, ah2, ah3, bh0, bh1);
                if (THREE_TERM) {
                    uint32_t bl0 = fu(Blo[br]), bl1 = fu(Blo[br + 4]);
                    mma8(acc[nt], ah0, ah1, ah2, ah3, bl0, bl1);
                    mma8(acc[nt], al0, al1, al2, al3, bh0, bh1);
                }
            }
        }
        __syncthreads();
        if (ch < 31) { sts(); __syncthreads(); }
    }

    const int r0 = m0 + wb + g, r1 = r0 + 8;
#pragma unroll
    for (int nt = 0; nt < 8; nt++) {
        *reinterpret_cast<float2*>(&outp[(size_t)r0 * H_ + nt * 8 + 2 * c]) =
            make_float2(acc[nt][0], acc[nt][1]);
        *reinterpret_cast<float2*>(&outp[(size_t)r1 * H_ + nt * 8 + 2 * c]) =
            make_float2(acc[nt][2], acc[nt][3]);
    }
}

constexpr uint32_t QKV3_SMEM = (128 * QPAD * 2 + 64 * QPAD * 2) * 4;  // 55296
constexpr uint32_t QKV1_SMEM = (128 * QPAD + 64 * QPAD) * 4;          // 27648

// ===========================================================================
// Kernel 2: flash attention, tf32 mma.sync.
// 128 threads (4 warps), 64 queries/CTA, warp = 16 query rows x 64 keys.
// QK^T: 3xTF32 (hi/lo).  PV: single TF32 (P and V rna-rounded).
// Online softmax entirely in registers (rows g, g+8 per thread, quad-reduced).
// Pads: Q/K/P stride 68 (≡4 mod 32), V stride 72 (≡8 mod 32) -> all fragment
// LDS patterns are bank-conflict-free.
// ===========================================================================
constexpr int PADA = 68;
constexpr int PADV = 72;
constexpr uint32_t ATT_SMEM =
    (4 * 64 * PADA + 64 * PADV + 4 * 16 * PADA) * 4;   // 105472 bytes

__global__ __launch_bounds__(128, 2) void attn_mma_kernel(
    float* __restrict__ out, const int* __restrict__ maskp)
{
    extern __shared__ float sa[];
    float* Qhi = sa;                      // [64][68]
    float* Qlo = Qhi + 64 * PADA;
    float* Khi = Qlo + 64 * PADA;
    float* Klo = Khi + 64 * PADA;
    float* Vs  = Klo + 64 * PADA;         // [64][72] (tf32-rounded)
    float* Ps  = Vs  + 64 * PADV;         // 4 x [16][68] warp-private

    const int tid  = threadIdx.x;
    const int warp = tid >> 5, lane = tid & 31;
    const int g = lane >> 2, c = lane & 3;
    const int wb = warp * 16;
    float* Pme = Ps + warp * 16 * PADA;

    // ---- balanced (jq, b) schedule: bids s and s+148 co-resident on one SM.
    // pairs sum to 28 cost-units; 40 singleton SMs get the 28..32-unit rows.
    const int bid = blockIdx.x;
    int jq, b;
    if (bid >= 148) {
        int p = bid - 148;
        if (p < 104) { jq = 26 - (p % 13); b = p / 13; }
        else         { jq = 13;            b = (p - 104) * 2 + 1; }
    } else if (bid >= 108) {
        int s = bid - 108;
        if (s < 32) { jq = 28 + (s >> 3); b = s & 7; }
        else        { jq = 27;            b = s - 32; }
    } else {
        if (bid < 104) { jq = bid % 13; b = bid / 13; }
        else           { jq = 13;       b = (bid - 104) * 2; }
    }
    const int t0   = jq * 64;
    const int mask = *maskp;

    const float* qb = g_q + (size_t)b * T_ * H_;
    const float* kb = g_k + (size_t)b * T_ * H_;
    const float* vb = g_v + (size_t)b * T_ * H_;

    // ---- load Q block (64x64), split hi/lo
#pragma unroll
    for (int i = 0; i < 8; i++) {
        int idx = tid + i * 128, r = idx >> 4, c4 = (idx & 15) * 4;
        float4 v = *reinterpret_cast<const float4*>(&qb[(size_t)(t0 + r) * H_ + c4]);
        float4 h, l; split4(v, h, l);
        *reinterpret_cast<float4*>(&Qhi[r * PADA + c4]) = h;
        *reinterpret_cast<float4*>(&Qlo[r * PADA + c4]) = l;
    }

    float rm[2] = {-CUDART_INF_F, -CUDART_INF_F};
    float rl[2] = {0.f, 0.f};
    float o[8][4];
#pragma unroll
    for (int nt = 0; nt < 8; nt++)
#pragma unroll
        for (int i = 0; i < 4; i++) o[nt][i] = 0.f;

    __syncthreads();

    const int jmax = mask ? jq : 31;
    for (int j = 0; j <= jmax; j++) {
        const int s0 = j * 64;

        // ---- K (hi/lo) and V (tf32-rounded) into smem
#pragma unroll
        for (int i = 0; i < 8; i++) {
            int idx = tid + i * 128, r = idx >> 4, c4 = (idx & 15) * 4;
            float4 kv = *reinterpret_cast<const float4*>(&kb[(size_t)(s0 + r) * H_ + c4]);
            float4 h, l; split4(kv, h, l);
            *reinterpret_cast<float4*>(&Khi[r * PADA + c4]) = h;
            *reinterpret_cast<float4*>(&Klo[r * PADA + c4]) = l;
            float4 vv = *reinterpret_cast<const float4*>(&vb[(size_t)(s0 + r) * H_ + c4]);
            *reinterpret_cast<float4*>(&Vs[r * PADV + c4]) = rnd4(vv);
        }
        __syncthreads();

        // ---- S = Q K^T (3-term tf32)
        float sacc[8][4];
#pragma unroll
        for (int nt = 0; nt < 8; nt++)
#pragma unroll
            for (int i = 0; i < 4; i++) sacc[nt][i] = 0.f;

#pragma unroll
        for (int kt = 0; kt < 8; kt++) {
            const int ka = kt * 8 + c;
            const int ra = (wb + g) * PADA, rb = (wb + g + 8) * PADA;
            uint32_t ah0 = fu(Qhi[ra + ka]),     ah1 = fu(Qhi[rb + ka]);
            uint32_t ah2 = fu(Qhi[ra + ka + 4]), ah3 = fu(Qhi[rb + ka + 4]);
            uint32_t al0 = fu(Qlo[ra + ka]),     al1 = fu(Qlo[rb + ka]);
            uint32_t al2 = fu(Qlo[ra + ka + 4]), al3 = fu(Qlo[rb + ka + 4]);
#pragma unroll
            for (int nt = 0; nt < 8; nt++) {
                const int br = (nt * 8 + g) * PADA + ka;
                uint32_t bh0 = fu(Khi[br]), bh1 = fu(Khi[br + 4]);
                uint32_t bl0 = fu(Klo[br]), bl1 = fu(Klo[br + 4]);
                mma8(sacc[nt], ah0, ah1, ah2, ah3, bh0, bh1);
                mma8(sacc[nt], ah0, ah1, ah2, ah3, bl0, bl1);
                mma8(sacc[nt], al0, al1, al2, al3, bh0, bh1);
            }
        }

        // ---- scale, mask
        const bool diag = (mask != 0) && (j == jq);
#pragma unroll
        for (int nt = 0; nt < 8; nt++) {
#pragma unroll
            for (int e = 0; e < 4; e++) {
                const int sg = s0 + nt * 8 + 2 * c + (e & 1);
                const int tg = t0 + wb + g + (e >> 1) * 8;
                float v = sacc[nt][e] * 8.0f;
                if (diag && sg > tg) v = -CUDART_INF_F;
                sacc[nt][e] = v;
            }
        }

        // ---- online softmax (rows g and g+8; quad = lanes sharing g)
        float alpha[2];
#pragma unroll
        for (int i = 0; i < 2; i++) {
            float m = -CUDART_INF_F;
#pragma unroll
            for (int nt = 0; nt < 8; nt++)
                m = fmaxf(m, fmaxf(sacc[nt][2 * i], sacc[nt][2 * i + 1]));
            m = fmaxf(m, __shfl_xor_sync(0xffffffffu, m, 1));
            m = fmaxf(m, __shfl_xor_sync(0xffffffffu, m, 2));
            const float mnew = fmaxf(rm[i], m);
            alpha[i] = __expf(rm[i] - mnew);
            float s = 0.f;
#pragma unroll
            for (int nt = 0; nt < 8; nt++) {
                float p0 = __expf(sacc[nt][2 * i]     - mnew);
                float p1 = __expf(sacc[nt][2 * i + 1] - mnew);
                sacc[nt][2 * i] = p0; sacc[nt][2 * i + 1] = p1;
                s += p0 + p1;
            }
            s += __shfl_xor_sync(0xffffffffu, s, 1);
            s += __shfl_xor_sync(0xffffffffu, s, 2);
            rl[i] = rl[i] * alpha[i] + s;
            rm[i] = mnew;
        }

        // ---- scale O, write P (tf32-rounded) to warp-private smem
#pragma unroll
        for (int nt = 0; nt < 8; nt++) {
            o[nt][0] *= alpha[0]; o[nt][1] *= alpha[0];
            o[nt][2] *= alpha[1]; o[nt][3] *= alpha[1];
            *reinterpret_cast<float2*>(&Pme[g * PADA + nt * 8 + 2 * c]) =
                make_float2(tf32r(sacc[nt][0]), tf32r(sacc[nt][1]));
            *reinterpret_cast<float2*>(&Pme[(g + 8) * PADA + nt * 8 + 2 * c]) =
                make_float2(tf32r(sacc[nt][2]), tf32r(sacc[nt][3]));
        }
        __syncwarp();

        // ---- O += P V (single tf32)
#pragma unroll
        for (int kt = 0; kt < 8; kt++) {
            const int ka = kt * 8 + c;
            uint32_t a0 = fu(Pme[g * PADA + ka]);
            uint32_t a1 = fu(Pme[(g + 8) * PADA + ka]);
            uint32_t a2 = fu(Pme[g * PADA + ka + 4]);
            uint32_t a3 = fu(Pme[(g + 8) * PADA + ka + 4]);
#pragma unroll
            for (int nt = 0; nt < 8; nt++) {
                uint32_t b0 = fu(Vs[ka * PADV + nt * 8 + g]);
                uint32_t b1 = fu(Vs[(ka + 4) * PADV + nt * 8 + g]);
                mma8(o[nt], a0, a1, a2, a3, b0, b1);
            }
        }
        __syncthreads();   // protect K/V/smem before next iteration overwrite
    }

    // ---- normalize, write out
    const float inv0 = 1.0f / rl[0], inv1 = 1.0f / rl[1];
    const size_t r0 = (size_t)b * T_ + t0 + wb + g;
#pragma unroll
    for (int nt = 0; nt < 8; nt++) {
        *reinterpret_cast<float2*>(&out[r0 * H_ + nt * 8 + 2 * c]) =
            make_float2(o[nt][0] * inv0, o[nt][1] * inv0);
        *reinterpret_cast<float2*>(&out[(r0 + 8) * H_ + nt * 8 + 2 * c]) =
            make_float2(o[nt][2] * inv1, o[nt][3] * inv1);
    }
}

// ---------------------------------------------------------------------------
extern "C" void kernel_launch(void* const* d_in, const int* in_sizes, int n_in,
                              void* d_out, int out_size)
{
    const float* x  = (const float*)d_in[0];
    const float* Wq = (const float*)d_in[1];
    const float* Wk = (const float*)d_in[2];
    const float* Wv = (const float*)d_in[3];
    const int* should_mask = (const int*)d_in[4];
    float* out = (float*)d_out;

    cudaFuncSetAttribute(qkv_mma_kernel<true>,
                         cudaFuncAttributeMaxDynamicSharedMemorySize, QKV3_SMEM);
    cudaFuncSetAttribute(qkv_mma_kernel<false>,
                         cudaFuncAttributeMaxDynamicSharedMemorySize, QKV1_SMEM);
    cudaFuncSetAttribute(attn_mma_kernel,
                         cudaFuncAttributeMaxDynamicSharedMemorySize, ATT_SMEM);

    dim3 qk_grid(MT / 128, 2);
    qkv_mma_kernel<true><<<qk_grid, 256, QKV3_SMEM>>>(x, Wq, Wk, Wv);
    qkv_mma_kernel<false><<<MT / 128, 256, QKV1_SMEM>>>(x, Wq, Wk, Wv);

    attn_mma_kernel<<<256, 128, ATT_SMEM>>>(out, should_mask);
}

// round 7
// speedup vs baseline: 1.3751x; 1.3751x over previous
#include <cuda_runtime.h>
#include <math.h>
#include <math_constants.h>
#include <cstdint>

// Problem shape (fixed by the reference)
constexpr int B_ = 8;
constexpr int T_ = 2048;
constexpr int E_ = 1024;
constexpr int H_ = 64;
constexpr int MT = B_ * T_;   // 16384 rows

// ---------------------------------------------------------------------------
// Device globals (no allocs allowed)
// Packed bf16 hi/lo weights (prep kernel) and q/k activations (qkv kernel).
// Word w of a row packs H-pairs (2w, 2w+1): low half = element 2w.
// ---------------------------------------------------------------------------
__device__ __align__(16) uint32_t g_wqh[64 * 512];
__device__ __align__(16) uint32_t g_wql[64 * 512];
__device__ __align__(16) uint32_t g_wkh[64 * 512];
__device__ __align__(16) uint32_t g_wkl[64 * 512];
__device__ __align__(16) float    g_wv [64 * 1024];   // tf32-rounded

__device__ __align__(16) uint32_t g_qbh[MT * 32];
__device__ __align__(16) uint32_t g_qbl[MT * 32];
__device__ __align__(16) uint32_t g_kbh[MT * 32];
__device__ __align__(16) uint32_t g_kbl[MT * 32];
__device__ __align__(16) float    g_vv [MT * 64];     // tf32-rounded

// ===========================================================================
// Baseline-PTX helpers (all valid at compute_103)
// ===========================================================================
__device__ __forceinline__ uint32_t smem_u32(const void* p) {
    uint32_t a;
    asm("{ .reg .u64 t; cvta.to.shared.u64 t, %1; cvt.u32.u64 %0, t; }"
        : "=r"(a) : "l"(p));
    return a;
}
__device__ __forceinline__ float tf32r(float v) {
    uint32_t u;
    asm("cvt.rna.tf32.f32 %0, %1;" : "=r"(u) : "f"(v));
    return __uint_as_float(u);
}
// Pack float2 -> bf16x2 hi word + bf16x2 lo word (hi = rn(v), lo = rn(v-hi))
__device__ __forceinline__ void bsplit2(float2 f, uint32_t& h, uint32_t& l) {
    asm("cvt.rn.bf16x2.f32 %0, %1, %2;" : "=r"(h) : "f"(f.y), "f"(f.x));
    float hx = __uint_as_float(h << 16);
    float hy = __uint_as_float(h & 0xffff0000u);
    asm("cvt.rn.bf16x2.f32 %0, %1, %2;" : "=r"(l) : "f"(f.y - hy), "f"(f.x - hx));
}
// D += A(16x16) * B(16x8), bf16 inputs, fp32 accum
__device__ __forceinline__ void mma16b(float* c,
                                       uint32_t a0, uint32_t a1, uint32_t a2, uint32_t a3,
                                       uint32_t b0, uint32_t b1) {
    asm volatile(
        "mma.sync.aligned.m16n8k16.row.col.f32.bf16.bf16.f32 "
        "{%0,%1,%2,%3}, {%4,%5,%6,%7}, {%8,%9}, {%0,%1,%2,%3};"
        : "+f"(c[0]), "+f"(c[1]), "+f"(c[2]), "+f"(c[3])
        : "r"(a0), "r"(a1), "r"(a2), "r"(a3), "r"(b0), "r"(b1));
}
// D += A(16x8) * B(8x8), tf32 inputs, fp32 accum
__device__ __forceinline__ void mma8(float* c,
                                     uint32_t a0, uint32_t a1, uint32_t a2, uint32_t a3,
                                     uint32_t b0, uint32_t b1) {
    asm volatile(
        "mma.sync.aligned.m16n8k8.row.col.f32.tf32.tf32.f32 "
        "{%0,%1,%2,%3}, {%4,%5,%6,%7}, {%8,%9}, {%0,%1,%2,%3};"
        : "+f"(c[0]), "+f"(c[1]), "+f"(c[2]), "+f"(c[3])
        : "r"(a0), "r"(a1), "r"(a2), "r"(a3), "r"(b0), "r"(b1));
}
__device__ __forceinline__ uint32_t fu(float v) { return __float_as_uint(v); }

#define CP16(d, s)  asm volatile("cp.async.ca.shared.global [%0], [%1], 16;" :: "r"(d), "l"(s))
#define CP_COMMIT() asm volatile("cp.async.commit_group;" ::: "memory")
#define CP_WAIT0()  asm volatile("cp.async.wait_group 0;" ::: "memory")
#define CP_WAIT1()  asm volatile("cp.async.wait_group 1;" ::: "memory")

// ===========================================================================
// Kernel 0: weight prep. Wq/Wk -> packed bf16 hi/lo; Wv -> tf32-rounded.
// grid (64, 3), 256 threads.
// ===========================================================================
__global__ void prep_kernel(const float* __restrict__ Wq,
                            const float* __restrict__ Wk,
                            const float* __restrict__ Wv)
{
    const int r = blockIdx.x, mat = blockIdx.y, tid = threadIdx.x;
    if (mat < 2) {
        const float* W = mat ? Wk : Wq;
        uint32_t* dh = mat ? g_wkh : g_wqh;
        uint32_t* dl = mat ? g_wkl : g_wql;
        for (int w = tid; w < 512; w += 256) {
            float2 f = *reinterpret_cast<const float2*>(&W[r * 1024 + 2 * w]);
            uint32_t h, l; bsplit2(f, h, l);
            dh[r * 512 + w] = h; dl[r * 512 + w] = l;
        }
    } else {
        for (int i = tid; i < 1024; i += 256)
            g_wv[r * 1024 + i] = tf32r(Wv[r * 1024 + i]);
    }
}

// ===========================================================================
// Kernel 1: merged QKV projection.
// grid 256 (64 rows each), 384 threads = 12 warps: warps 0-3 Q, 4-7 K, 8-11 V.
// Q/K: 3-term bf16 m16n8k16; V: 1-term tf32 m16n8k8.
// Double-buffered cp.async staging.
// ===========================================================================
constexpr int XSTR = 40;   // floats; raw A tile rows
constexpr int WSTR = 20;   // u32;    packed B-frag banks (4g+c) conflict-free
constexpr int VSTR = 36;   // floats; tf32 B-frag banks (4g+c) conflict-free
constexpr uint32_t OX   = 0;
constexpr uint32_t OWH0 = 10240;
constexpr uint32_t OWL0 = 15360;
constexpr uint32_t OWH1 = 20480;
constexpr uint32_t OWL1 = 25600;
constexpr uint32_t OWV  = 30720;
constexpr uint32_t QSTG = 39936;
constexpr uint32_t QKV_SMEM = 2 * QSTG;   // 79872 bytes

__global__ __launch_bounds__(384) void qkv_kernel(const float* __restrict__ x)
{
    extern __shared__ char sm8[];
    const uint32_t sb = smem_u32(sm8);
    const int tid  = threadIdx.x;
    const int wid  = tid >> 5, lane = tid & 31;
    const int g = lane >> 2, c = lane & 3;
    const int mat = wid >> 2;          // 0=Q, 1=K, 2=V
    const int wb  = (wid & 3) * 16;
    const int m0  = blockIdx.x * 64;

    auto issue = [&](int ch, int st) {
        const uint32_t s0 = sb + (uint32_t)st * QSTG;
        const int k0 = ch * 32;
        for (int i = tid; i < 2048; i += 384) {
            if (i < 512) {
                int r = i >> 3, sg = i & 7;
                CP16(s0 + OX + (uint32_t)(r * XSTR + sg * 4) * 4,
                     (const char*)(x + (size_t)(m0 + r) * E_ + k0 + sg * 4));
            } else if (i < 1536) {
                int t = i - 512, arr = t >> 8, u = t & 255;
                int r = u >> 2, sg = u & 3;
                const uint32_t* src =
                    (arr == 0 ? g_wqh : arr == 1 ? g_wql : arr == 2 ? g_wkh : g_wkl)
                    + r * 512 + ch * 16 + sg * 4;
                uint32_t off = (arr == 0 ? OWH0 : arr == 1 ? OWL0 : arr == 2 ? OWH1 : OWL1);
                CP16(s0 + off + (uint32_t)(r * WSTR + sg * 4) * 4, (const char*)src);
            } else {
                int t = i - 1536, r = t >> 3, sg = t & 7;
                CP16(s0 + OWV + (uint32_t)(r * VSTR + sg * 4) * 4,
                     (const char*)(g_wv + r * 1024 + k0 + sg * 4));
            }
        }
        CP_COMMIT();
    };

    float acc[8][4];
#pragma unroll
    for (int nt = 0; nt < 8; nt++)
#pragma unroll
        for (int i = 0; i < 4; i++) acc[nt][i] = 0.f;

    issue(0, 0);

    for (int ch = 0; ch < 32; ch++) {
        const int st = ch & 1;
        if (ch + 1 < 32) { issue(ch + 1, st ^ 1); CP_WAIT1(); } else { CP_WAIT0(); }
        __syncthreads();

        const char* stage = sm8 + (size_t)st * QSTG;
        const float* Xf = (const float*)(stage + OX);

        if (mat < 2) {
            const uint32_t* WH = (const uint32_t*)(stage + (mat ? OWH1 : OWH0));
            const uint32_t* WL = (const uint32_t*)(stage + (mat ? OWL1 : OWL0));
#pragma unroll
            for (int kt = 0; kt < 2; kt++) {
                const int cb = kt * 16 + 2 * c;
                float2 f00 = *(const float2*)&Xf[(wb + g) * XSTR + cb];
                float2 f10 = *(const float2*)&Xf[(wb + g + 8) * XSTR + cb];
                float2 f01 = *(const float2*)&Xf[(wb + g) * XSTR + cb + 8];
                float2 f11 = *(const float2*)&Xf[(wb + g + 8) * XSTR + cb + 8];
                uint32_t ah0, al0, ah1, al1, ah2, al2, ah3, al3;
                bsplit2(f00, ah0, al0); bsplit2(f10, ah1, al1);
                bsplit2(f01, ah2, al2); bsplit2(f11, ah3, al3);
#pragma unroll
                for (int nt = 0; nt < 8; nt++) {
                    const int br = (nt * 8 + g) * WSTR + kt * 8 + c;
                    uint32_t bh0 = WH[br], bh1 = WH[br + 4];
                    uint32_t bl0 = WL[br], bl1 = WL[br + 4];
                    mma16b(acc[nt], ah0, ah1, ah2, ah3, bh0, bh1);
                    mma16b(acc[nt], ah0, ah1, ah2, ah3, bl0, bl1);
                    mma16b(acc[nt], al0, al1, al2, al3, bh0, bh1);
                }
            }
        } else {
            const float* WV = (const float*)(stage + OWV);
#pragma unroll
            for (int kt = 0; kt < 4; kt++) {
                const int ka = kt * 8 + c;
                uint32_t a0 = fu(tf32r(Xf[(wb + g) * XSTR + ka]));
                uint32_t a1 = fu(tf32r(Xf[(wb + g + 8) * XSTR + ka]));
                uint32_t a2 = fu(tf32r(Xf[(wb + g) * XSTR + ka + 4]));
                uint32_t a3 = fu(tf32r(Xf[(wb + g + 8) * XSTR + ka + 4]));
#pragma unroll
                for (int nt = 0; nt < 8; nt++) {
                    const int br = (nt * 8 + g) * VSTR + ka;
                    mma8(acc[nt], a0, a1, a2, a3, fu(WV[br]), fu(WV[br + 4]));
                }
            }
        }
        __syncthreads();
    }

    // ---- epilogue
    const int r0 = m0 + wb + g, r1 = r0 + 8;
    if (mat < 2) {
        uint32_t* dh = mat ? g_kbh : g_qbh;
        uint32_t* dl = mat ? g_kbl : g_qbl;
#pragma unroll
        for (int nt = 0; nt < 8; nt++) {
            const int w = nt * 4 + c;
            uint32_t h, l;
            bsplit2(make_float2(acc[nt][0], acc[nt][1]), h, l);
            dh[(size_t)r0 * 32 + w] = h; dl[(size_t)r0 * 32 + w] = l;
            bsplit2(make_float2(acc[nt][2], acc[nt][3]), h, l);
            dh[(size_t)r1 * 32 + w] = h; dl[(size_t)r1 * 32 + w] = l;
        }
    } else {
#pragma unroll
        for (int nt = 0; nt < 8; nt++) {
            *(float2*)&g_vv[(size_t)r0 * 64 + nt * 8 + 2 * c] =
                make_float2(tf32r(acc[nt][0]), tf32r(acc[nt][1]));
            *(float2*)&g_vv[(size_t)r1 * 64 + nt * 8 + 2 * c] =
                make_float2(tf32r(acc[nt][2]), tf32r(acc[nt][3]));
        }
    }
}

// ===========================================================================
// Kernel 2: flash attention.
// 128 threads (4 warps), 64 queries/CTA, warp = 16 query rows x 64 keys.
// QK^T: 3-term bf16 m16n8k16 (operands pre-packed).  PV: 1-term tf32.
// cp.async double-buffered K/V stages. Register online softmax.
// Strides (words): Q/K packed 36 (banks 4g+c), V fp32 72 (banks 8c+g),
// P fp32 68 (banks 4g+c) — all fragment LDS conflict-free.
// ===========================================================================
constexpr uint32_t OQBH = 0;
constexpr uint32_t OQBL = 9216;
constexpr uint32_t OKBH = 18432;   // + st*9216
constexpr uint32_t OKBL = 36864;   // + st*9216
constexpr uint32_t OV   = 55296;   // + st*18432
constexpr uint32_t OP   = 92160;   // + warp*4352  (16 rows x 68 floats)
constexpr uint32_t PWSZ = 16 * 68 * 4;          // 4352 bytes per warp
constexpr uint32_t ATT_SMEM = OP + 4 * PWSZ;    // 109568 bytes

__global__ __launch_bounds__(128, 2) void attn_kernel(
    float* __restrict__ out, const int* __restrict__ maskp)
{
    extern __shared__ char sma[];
    const uint32_t sb = smem_u32(sma);
    const int tid  = threadIdx.x;
    const int warp = tid >> 5, lane = tid & 31;
    const int g = lane >> 2, c = lane & 3;
    const int wb = warp * 16;

    // ---- balanced (jq, b) schedule: bids s and s+148 co-resident on one SM.
    const int bid = blockIdx.x;
    int jq, b;
    if (bid >= 148) {
        int p = bid - 148;
        if (p < 104) { jq = 26 - (p % 13); b = p / 13; }
        else         { jq = 13;            b = (p - 104) * 2 + 1; }
    } else if (bid >= 108) {
        int s = bid - 108;
        if (s < 32) { jq = 28 + (s >> 3); b = s & 7; }
        else        { jq = 27;            b = s - 32; }
    } else {
        if (bid < 104) { jq = bid % 13; b = bid / 13; }
        else           { jq = 13;       b = (bid - 104) * 2; }
    }
    const int t0   = jq * 64;
    const int mask = *maskp;
    const size_t roff = (size_t)b * T_;

    auto issue_kv = [&](int j, int st) {
        const int s0r = j * 64;
        const uint32_t kb = sb + OKBH + (uint32_t)st * 9216;
        const uint32_t kl = sb + OKBL + (uint32_t)st * 9216;
        const uint32_t vv = sb + OV   + (uint32_t)st * 18432;
        for (int i = tid; i < 2048; i += 128) {
            if (i < 512) {
                int r = i >> 3, sg = i & 7;
                CP16(kb + (uint32_t)(r * 36 + sg * 4) * 4,
                     (const char*)(g_kbh + (roff + s0r + r) * 32 + sg * 4));
            } else if (i < 1024) {
                int t = i - 512, r = t >> 3, sg = t & 7;
                CP16(kl + (uint32_t)(r * 36 + sg * 4) * 4,
                     (const char*)(g_kbl + (roff + s0r + r) * 32 + sg * 4));
            } else {
                int t = i - 1024, r = t >> 4, sg = t & 15;
                CP16(vv + (uint32_t)(r * 72 + sg * 4) * 4,
                     (const char*)(g_vv + (roff + s0r + r) * 64 + sg * 4));
            }
        }
        CP_COMMIT();
    };

    // ---- prologue: Q (packed) + first K/V stage, one group
    for (int i = tid; i < 1024; i += 128) {
        int arr = i >> 9, t = i & 511, r = t >> 3, sg = t & 7;
        const uint32_t* src = (arr ? g_qbl : g_qbh) + (roff + t0 + r) * 32 + sg * 4;
        CP16(sb + (arr ? OQBL : OQBH) + (uint32_t)(r * 36 + sg * 4) * 4,
             (const char*)src);
    }
    issue_kv(0, 0);

    const uint32_t* Qbh = (const uint32_t*)(sma + OQBH);
    const uint32_t* Qbl = (const uint32_t*)(sma + OQBL);
    float* Pme = (float*)(sma + OP + (uint32_t)warp * PWSZ);

    float rm[2] = {-CUDART_INF_F, -CUDART_INF_F};
    float rl[2] = {0.f, 0.f};
    float o[8][4];
#pragma unroll
    for (int nt = 0; nt < 8; nt++)
#pragma unroll
        for (int i = 0; i < 4; i++) o[nt][i] = 0.f;

    const int jmax = mask ? jq : 31;
    for (int j = 0; j <= jmax; j++) {
        const int st = j & 1;
        if (j + 1 <= jmax) { issue_kv(j + 1, st ^ 1); CP_WAIT1(); } else { CP_WAIT0(); }
        __syncthreads();

        const uint32_t* Kbh = (const uint32_t*)(sma + OKBH + (size_t)st * 9216);
        const uint32_t* Kbl = (const uint32_t*)(sma + OKBL + (size_t)st * 9216);
        const float*    Vst = (const float*)(sma + OV + (size_t)st * 18432);
        const int s0 = j * 64;

        // ---- S = Q K^T (3-term bf16, k16)
        float sacc[8][4];
#pragma unroll
        for (int nt = 0; nt < 8; nt++)
#pragma unroll
            for (int i = 0; i < 4; i++) sacc[nt][i] = 0.f;

#pragma unroll
        for (int kt = 0; kt < 4; kt++) {
            const int ra = (wb + g) * 36 + kt * 8 + c;
            const int rb = (wb + g + 8) * 36 + kt * 8 + c;
            uint32_t ah0 = Qbh[ra], ah1 = Qbh[rb], ah2 = Qbh[ra + 4], ah3 = Qbh[rb + 4];
            uint32_t al0 = Qbl[ra], al1 = Qbl[rb], al2 = Qbl[ra + 4], al3 = Qbl[rb + 4];
#pragma unroll
            for (int nt = 0; nt < 8; nt++) {
                const int br = (nt * 8 + g) * 36 + kt * 8 + c;
                uint32_t bh0 = Kbh[br], bh1 = Kbh[br + 4];
                uint32_t bl0 = Kbl[br], bl1 = Kbl[br + 4];
                mma16b(sacc[nt], ah0, ah1, ah2, ah3, bh0, bh1);
                mma16b(sacc[nt], ah0, ah1, ah2, ah3, bl0, bl1);
                mma16b(sacc[nt], al0, al1, al2, al3, bh0, bh1);
            }
        }

        // ---- scale, mask
        const bool diag = (mask != 0) && (j == jq);
#pragma unroll
        for (int nt = 0; nt < 8; nt++) {
#pragma unroll
            for (int e = 0; e < 4; e++) {
                const int sg = s0 + nt * 8 + 2 * c + (e & 1);
                const int tg = t0 + wb + g + (e >> 1) * 8;
                float v = sacc[nt][e] * 8.0f;
                if (diag && sg > tg) v = -CUDART_INF_F;
                sacc[nt][e] = v;
            }
        }

        // ---- online softmax (rows g and g+8; quad reduce over c)
        float alpha[2];
#pragma unroll
        for (int i = 0; i < 2; i++) {
            float m = -CUDART_INF_F;
#pragma unroll
            for (int nt = 0; nt < 8; nt++)
                m = fmaxf(m, fmaxf(sacc[nt][2 * i], sacc[nt][2 * i + 1]));
            m = fmaxf(m, __shfl_xor_sync(0xffffffffu, m, 1));
            m = fmaxf(m, __shfl_xor_sync(0xffffffffu, m, 2));
            const float mnew = fmaxf(rm[i], m);
            alpha[i] = __expf(rm[i] - mnew);
            float s = 0.f;
#pragma unroll
            for (int nt = 0; nt < 8; nt++) {
                float p0 = __expf(sacc[nt][2 * i]     - mnew);
                float p1 = __expf(sacc[nt][2 * i + 1] - mnew);
                sacc[nt][2 * i] = p0; sacc[nt][2 * i + 1] = p1;
                s += p0 + p1;
            }
            s += __shfl_xor_sync(0xffffffffu, s, 1);
            s += __shfl_xor_sync(0xffffffffu, s, 2);
            rl[i] = rl[i] * alpha[i] + s;
            rm[i] = mnew;
        }

        // ---- scale O, stage P (tf32) warp-private (stride 68)
#pragma unroll
        for (int nt = 0; nt < 8; nt++) {
            o[nt][0] *= alpha[0]; o[nt][1] *= alpha[0];
            o[nt][2] *= alpha[1]; o[nt][3] *= alpha[1];
            *(float2*)&Pme[g * 68 + nt * 8 + 2 * c] =
                make_float2(tf32r(sacc[nt][0]), tf32r(sacc[nt][1]));
            *(float2*)&Pme[(g + 8) * 68 + nt * 8 + 2 * c] =
                make_float2(tf32r(sacc[nt][2]), tf32r(sacc[nt][3]));
        }
        __syncwarp();

        // ---- O += P V (single tf32, k8)
#pragma unroll
        for (int kt = 0; kt < 8; kt++) {
            const int ka = kt * 8 + c;
            uint32_t a0 = fu(Pme[g * 68 + ka]);
            uint32_t a1 = fu(Pme[(g + 8) * 68 + ka]);
            uint32_t a2 = fu(Pme[g * 68 + ka + 4]);
            uint32_t a3 = fu(Pme[(g + 8) * 68 + ka + 4]);
#pragma unroll
            for (int nt = 0; nt < 8; nt++) {
                uint32_t b0 = fu(Vst[ka * 72 + nt * 8 + g]);
                uint32_t b1 = fu(Vst[(ka + 4) * 72 + nt * 8 + g]);
                mma8(o[nt], a0, a1, a2, a3, b0, b1);
            }
        }
        __syncthreads();
    }

    // ---- normalize, write out
    const float inv0 = 1.0f / rl[0], inv1 = 1.0f / rl[1];
    const size_t r0 = roff + t0 + wb + g;
#pragma unroll
    for (int nt = 0; nt < 8; nt++) {
        *(float2*)&out[r0 * H_ + nt * 8 + 2 * c] =
            make_float2(o[nt][0] * inv0, o[nt][1] * inv0);
        *(float2*)&out[(r0 + 8) * H_ + nt * 8 + 2 * c] =
            make_float2(o[nt][2] * inv1, o[nt][3] * inv1);
    }
}

// ---------------------------------------------------------------------------
extern "C" void kernel_launch(void* const* d_in, const int* in_sizes, int n_in,
                              void* d_out, int out_size)
{
    const float* x  = (const float*)d_in[0];
    const float* Wq = (const float*)d_in[1];
    const float* Wk = (const float*)d_in[2];
    const float* Wv = (const float*)d_in[3];
    const int* should_mask = (const int*)d_in[4];
    float* out = (float*)d_out;

    cudaFuncSetAttribute(qkv_kernel,
                         cudaFuncAttributeMaxDynamicSharedMemorySize, QKV_SMEM);
    cudaFuncSetAttribute(attn_kernel,
                         cudaFuncAttributeMaxDynamicSharedMemorySize, ATT_SMEM);

    prep_kernel<<<dim3(64, 3), 256>>>(Wq, Wk, Wv);
    qkv_kernel<<<256, 384, QKV_SMEM>>>(x);
    attn_kernel<<<256, 128, ATT_SMEM>>>(out, should_mask);
}

// round 8
// speedup vs baseline: 1.3811x; 1.0044x over previous
#include <cuda_runtime.h>
#include <math.h>
#include <math_constants.h>
#include <cstdint>

// Problem shape (fixed by the reference)
constexpr int B_ = 8;
constexpr int T_ = 2048;
constexpr int E_ = 1024;
constexpr int H_ = 64;
constexpr int MT = B_ * T_;   // 16384 rows

// ---------------------------------------------------------------------------
// Device globals (no allocs allowed)
// Packed bf16 hi/lo weights (prep kernel) and q/k activations (qkv kernel).
// Word w of a row packs H-pairs (2w, 2w+1): low half = element 2w.
// ---------------------------------------------------------------------------
__device__ __align__(16) uint32_t g_wqh[64 * 512];
__device__ __align__(16) uint32_t g_wql[64 * 512];
__device__ __align__(16) uint32_t g_wkh[64 * 512];
__device__ __align__(16) uint32_t g_wkl[64 * 512];
__device__ __align__(16) float    g_wv [64 * 1024];   // tf32-rounded

__device__ __align__(16) uint32_t g_qbh[MT * 32];
__device__ __align__(16) uint32_t g_qbl[MT * 32];
__device__ __align__(16) uint32_t g_kbh[MT * 32];
__device__ __align__(16) uint32_t g_kbl[MT * 32];
__device__ __align__(16) float    g_vv [MT * 64];     // tf32-rounded

// ===========================================================================
// Baseline-PTX helpers (all valid at compute_103)
// ===========================================================================
__device__ __forceinline__ uint32_t smem_u32(const void* p) {
    uint32_t a;
    asm("{ .reg .u64 t; cvta.to.shared.u64 t, %1; cvt.u32.u64 %0, t; }"
        : "=r"(a) : "l"(p));
    return a;
}
__device__ __forceinline__ float tf32r(float v) {
    uint32_t u;
    asm("cvt.rna.tf32.f32 %0, %1;" : "=r"(u) : "f"(v));
    return __uint_as_float(u);
}
// Pack float2 -> bf16x2 hi word + bf16x2 lo word (hi = rn(v), lo = rn(v-hi))
__device__ __forceinline__ void bsplit2(float2 f, uint32_t& h, uint32_t& l) {
    asm("cvt.rn.bf16x2.f32 %0, %1, %2;" : "=r"(h) : "f"(f.y), "f"(f.x));
    float hx = __uint_as_float(h << 16);
    float hy = __uint_as_float(h & 0xffff0000u);
    asm("cvt.rn.bf16x2.f32 %0, %1, %2;" : "=r"(l) : "f"(f.y - hy), "f"(f.x - hx));
}
// D += A(16x16) * B(16x8), bf16 inputs, fp32 accum
__device__ __forceinline__ void mma16b(float* c,
                                       uint32_t a0, uint32_t a1, uint32_t a2, uint32_t a3,
                                       uint32_t b0, uint32_t b1) {
    asm volatile(
        "mma.sync.aligned.m16n8k16.row.col.f32.bf16.bf16.f32 "
        "{%0,%1,%2,%3}, {%4,%5,%6,%7}, {%8,%9}, {%0,%1,%2,%3};"
        : "+f"(c[0]), "+f"(c[1]), "+f"(c[2]), "+f"(c[3])
        : "r"(a0), "r"(a1), "r"(a2), "r"(a3), "r"(b0), "r"(b1));
}
// D += A(16x8) * B(8x8), tf32 inputs, fp32 accum
__device__ __forceinline__ void mma8(float* c,
                                     uint32_t a0, uint32_t a1, uint32_t a2, uint32_t a3,
                                     uint32_t b0, uint32_t b1) {
    asm volatile(
        "mma.sync.aligned.m16n8k8.row.col.f32.tf32.tf32.f32 "
        "{%0,%1,%2,%3}, {%4,%5,%6,%7}, {%8,%9}, {%0,%1,%2,%3};"
        : "+f"(c[0]), "+f"(c[1]), "+f"(c[2]), "+f"(c[3])
        : "r"(a0), "r"(a1), "r"(a2), "r"(a3), "r"(b0), "r"(b1));
}
__device__ __forceinline__ uint32_t fu(float v) { return __float_as_uint(v); }

#define CP16(d, s)  asm volatile("cp.async.ca.shared.global [%0], [%1], 16;" :: "r"(d), "l"(s))
#define CP_COMMIT() asm volatile("cp.async.commit_group;" ::: "memory")
#define CP_WAIT0()  asm volatile("cp.async.wait_group 0;" ::: "memory")
#define CP_WAIT1()  asm volatile("cp.async.wait_group 1;" ::: "memory")

// ===========================================================================
// Kernel 0: weight prep. Wq/Wk -> packed bf16 hi/lo; Wv -> tf32-rounded.
// ===========================================================================
__global__ void prep_kernel(const float* __restrict__ Wq,
                            const float* __restrict__ Wk,
                            const float* __restrict__ Wv)
{
    const int r = blockIdx.x, mat = blockIdx.y, tid = threadIdx.x;
    if (mat < 2) {
        const float* W = mat ? Wk : Wq;
        uint32_t* dh = mat ? g_wkh : g_wqh;
        uint32_t* dl = mat ? g_wkl : g_wql;
        for (int w = tid; w < 512; w += 256) {
            float2 f = *reinterpret_cast<const float2*>(&W[r * 1024 + 2 * w]);
            uint32_t h, l; bsplit2(f, h, l);
            dh[r * 512 + w] = h; dl[r * 512 + w] = l;
        }
    } else {
        for (int i = tid; i < 1024; i += 256)
            g_wv[r * 1024 + i] = tf32r(Wv[r * 1024 + i]);
    }
}

// ===========================================================================
// Kernel 1: merged QKV projection.
// grid 256 (64 rows each), 384 threads = 12 warps: warps 0-3 Q, 4-7 K, 8-11 V.
// Q/K: 3-term bf16 m16n8k16 issued as 3 term-passes (same-acc distance = 8).
// V: 1-term tf32 m16n8k8.  Double-buffered cp.async staging.
// ===========================================================================
constexpr int XSTR = 40;   // floats; raw A tile rows
constexpr int WSTR = 20;   // u32;    packed B-frag banks (4g+c) conflict-free
constexpr int VSTR = 36;   // floats; tf32 B-frag banks (4g+c) conflict-free
constexpr uint32_t OX   = 0;
constexpr uint32_t OWH0 = 10240;
constexpr uint32_t OWL0 = 15360;
constexpr uint32_t OWH1 = 20480;
constexpr uint32_t OWL1 = 25600;
constexpr uint32_t OWV  = 30720;
constexpr uint32_t QSTG = 39936;
constexpr uint32_t QKV_SMEM = 2 * QSTG;   // 79872 bytes

__global__ __launch_bounds__(384) void qkv_kernel(const float* __restrict__ x)
{
    extern __shared__ char sm8[];
    const uint32_t sb = smem_u32(sm8);
    const int tid  = threadIdx.x;
    const int wid  = tid >> 5, lane = tid & 31;
    const int g = lane >> 2, c = lane & 3;
    const int mat = wid >> 2;          // 0=Q, 1=K, 2=V
    const int wb  = (wid & 3) * 16;
    const int m0  = blockIdx.x * 64;

    auto issue = [&](int ch, int st) {
        const uint32_t s0 = sb + (uint32_t)st * QSTG;
        const int k0 = ch * 32;
        for (int i = tid; i < 2048; i += 384) {
            if (i < 512) {
                int r = i >> 3, sg = i & 7;
                CP16(s0 + OX + (uint32_t)(r * XSTR + sg * 4) * 4,
                     (const char*)(x + (size_t)(m0 + r) * E_ + k0 + sg * 4));
            } else if (i < 1536) {
                int t = i - 512, arr = t >> 8, u = t & 255;
                int r = u >> 2, sg = u & 3;
                const uint32_t* src =
                    (arr == 0 ? g_wqh : arr == 1 ? g_wql : arr == 2 ? g_wkh : g_wkl)
                    + r * 512 + ch * 16 + sg * 4;
                uint32_t off = (arr == 0 ? OWH0 : arr == 1 ? OWL0 : arr == 2 ? OWH1 : OWL1);
                CP16(s0 + off + (uint32_t)(r * WSTR + sg * 4) * 4, (const char*)src);
            } else {
                int t = i - 1536, r = t >> 3, sg = t & 7;
                CP16(s0 + OWV + (uint32_t)(r * VSTR + sg * 4) * 4,
                     (const char*)(g_wv + r * 1024 + k0 + sg * 4));
            }
        }
        CP_COMMIT();
    };

    float acc[8][4];
#pragma unroll
    for (int nt = 0; nt < 8; nt++)
#pragma unroll
        for (int i = 0; i < 4; i++) acc[nt][i] = 0.f;

    issue(0, 0);

    for (int ch = 0; ch < 32; ch++) {
        const int st = ch & 1;
        if (ch + 1 < 32) { issue(ch + 1, st ^ 1); CP_WAIT1(); } else { CP_WAIT0(); }
        __syncthreads();

        const char* stage = sm8 + (size_t)st * QSTG;
        const float* Xf = (const float*)(stage + OX);

        if (mat < 2) {
            const uint32_t* WH = (const uint32_t*)(stage + (mat ? OWH1 : OWH0));
            const uint32_t* WL = (const uint32_t*)(stage + (mat ? OWL1 : OWL0));
            // A fragments for both kt, hi and lo
            uint32_t ah[2][4], al[2][4];
#pragma unroll
            for (int kt = 0; kt < 2; kt++) {
                const int cb = kt * 16 + 2 * c;
                float2 f00 = *(const float2*)&Xf[(wb + g) * XSTR + cb];
                float2 f10 = *(const float2*)&Xf[(wb + g + 8) * XSTR + cb];
                float2 f01 = *(const float2*)&Xf[(wb + g) * XSTR + cb + 8];
                float2 f11 = *(const float2*)&Xf[(wb + g + 8) * XSTR + cb + 8];
                bsplit2(f00, ah[kt][0], al[kt][0]);
                bsplit2(f10, ah[kt][1], al[kt][1]);
                bsplit2(f01, ah[kt][2], al[kt][2]);
                bsplit2(f11, ah[kt][3], al[kt][3]);
            }
            // term pass 1: hi x hi  (same-acc distance = 8 mmas)
#pragma unroll
            for (int kt = 0; kt < 2; kt++)
#pragma unroll
                for (int nt = 0; nt < 8; nt++) {
                    const int br = (nt * 8 + g) * WSTR + kt * 8 + c;
                    mma16b(acc[nt], ah[kt][0], ah[kt][1], ah[kt][2], ah[kt][3],
                           WH[br], WH[br + 4]);
                }
            // term pass 2: lo x hi
#pragma unroll
            for (int kt = 0; kt < 2; kt++)
#pragma unroll
                for (int nt = 0; nt < 8; nt++) {
                    const int br = (nt * 8 + g) * WSTR + kt * 8 + c;
                    mma16b(acc[nt], al[kt][0], al[kt][1], al[kt][2], al[kt][3],
                           WH[br], WH[br + 4]);
                }
            // term pass 3: hi x lo
#pragma unroll
            for (int kt = 0; kt < 2; kt++)
#pragma unroll
                for (int nt = 0; nt < 8; nt++) {
                    const int br = (nt * 8 + g) * WSTR + kt * 8 + c;
                    mma16b(acc[nt], ah[kt][0], ah[kt][1], ah[kt][2], ah[kt][3],
                           WL[br], WL[br + 4]);
                }
        } else {
            const float* WV = (const float*)(stage + OWV);
#pragma unroll
            for (int kt = 0; kt < 4; kt++) {
                const int ka = kt * 8 + c;
                uint32_t a0 = fu(tf32r(Xf[(wb + g) * XSTR + ka]));
                uint32_t a1 = fu(tf32r(Xf[(wb + g + 8) * XSTR + ka]));
                uint32_t a2 = fu(tf32r(Xf[(wb + g) * XSTR + ka + 4]));
                uint32_t a3 = fu(tf32r(Xf[(wb + g + 8) * XSTR + ka + 4]));
#pragma unroll
                for (int nt = 0; nt < 8; nt++) {
                    const int br = (nt * 8 + g) * VSTR + ka;
                    mma8(acc[nt], a0, a1, a2, a3, fu(WV[br]), fu(WV[br + 4]));
                }
            }
        }
        __syncthreads();
    }

    // ---- epilogue
    const int r0 = m0 + wb + g, r1 = r0 + 8;
    if (mat < 2) {
        uint32_t* dh = mat ? g_kbh : g_qbh;
        uint32_t* dl = mat ? g_kbl : g_qbl;
#pragma unroll
        for (int nt = 0; nt < 8; nt++) {
            const int w = nt * 4 + c;
            uint32_t h, l;
            bsplit2(make_float2(acc[nt][0], acc[nt][1]), h, l);
            dh[(size_t)r0 * 32 + w] = h; dl[(size_t)r0 * 32 + w] = l;
            bsplit2(make_float2(acc[nt][2], acc[nt][3]), h, l);
            dh[(size_t)r1 * 32 + w] = h; dl[(size_t)r1 * 32 + w] = l;
        }
    } else {
#pragma unroll
        for (int nt = 0; nt < 8; nt++) {
            *(float2*)&g_vv[(size_t)r0 * 64 + nt * 8 + 2 * c] =
                make_float2(tf32r(acc[nt][0]), tf32r(acc[nt][1]));
            *(float2*)&g_vv[(size_t)r1 * 64 + nt * 8 + 2 * c] =
                make_float2(tf32r(acc[nt][2]), tf32r(acc[nt][3]));
        }
    }
}

// ===========================================================================
// Kernel 2: flash attention.
// 128 threads (4 warps), 64 queries/CTA, warp = 16 query rows x 64 keys.
// QK^T: 3-term bf16 m16n8k16 issued as 3 term-passes; Q frags hoisted out
// of the key loop (loop-invariant).  PV: 1-term tf32.
// cp.async double-buffered K/V stages. Register online softmax.
// ===========================================================================
constexpr uint32_t OQBH = 0;
constexpr uint32_t OQBL = 9216;
constexpr uint32_t OKBH = 18432;   // + st*9216
constexpr uint32_t OKBL = 36864;   // + st*9216
constexpr uint32_t OV   = 55296;   // + st*18432
constexpr uint32_t OP   = 92160;   // + warp*4352  (16 rows x 68 floats)
constexpr uint32_t PWSZ = 16 * 68 * 4;          // 4352 bytes per warp
constexpr uint32_t ATT_SMEM = OP + 4 * PWSZ;    // 109568 bytes

__global__ __launch_bounds__(128, 2) void attn_kernel(
    float* __restrict__ out, const int* __restrict__ maskp)
{
    extern __shared__ char sma[];
    const uint32_t sb = smem_u32(sma);
    const int tid  = threadIdx.x;
    const int warp = tid >> 5, lane = tid & 31;
    const int g = lane >> 2, c = lane & 3;
    const int wb = warp * 16;

    // ---- balanced (jq, b) schedule: bids s and s+148 co-resident on one SM.
    const int bid = blockIdx.x;
    int jq, b;
    if (bid >= 148) {
        int p = bid - 148;
        if (p < 104) { jq = 26 - (p % 13); b = p / 13; }
        else         { jq = 13;            b = (p - 104) * 2 + 1; }
    } else if (bid >= 108) {
        int s = bid - 108;
        if (s < 32) { jq = 28 + (s >> 3); b = s & 7; }
        else        { jq = 27;            b = s - 32; }
    } else {
        if (bid < 104) { jq = bid % 13; b = bid / 13; }
        else           { jq = 13;       b = (bid - 104) * 2; }
    }
    const int t0   = jq * 64;
    const int mask = *maskp;
    const size_t roff = (size_t)b * T_;

    auto issue_kv = [&](int j, int st) {
        const int s0r = j * 64;
        const uint32_t kb = sb + OKBH + (uint32_t)st * 9216;
        const uint32_t kl = sb + OKBL + (uint32_t)st * 9216;
        const uint32_t vv = sb + OV   + (uint32_t)st * 18432;
        for (int i = tid; i < 2048; i += 128) {
            if (i < 512) {
                int r = i >> 3, sg = i & 7;
                CP16(kb + (uint32_t)(r * 36 + sg * 4) * 4,
                     (const char*)(g_kbh + (roff + s0r + r) * 32 + sg * 4));
            } else if (i < 1024) {
                int t = i - 512, r = t >> 3, sg = t & 7;
                CP16(kl + (uint32_t)(r * 36 + sg * 4) * 4,
                     (const char*)(g_kbl + (roff + s0r + r) * 32 + sg * 4));
            } else {
                int t = i - 1024, r = t >> 4, sg = t & 15;
                CP16(vv + (uint32_t)(r * 72 + sg * 4) * 4,
                     (const char*)(g_vv + (roff + s0r + r) * 64 + sg * 4));
            }
        }
        CP_COMMIT();
    };

    // ---- prologue: Q (packed) + first K/V stage, one group
    for (int i = tid; i < 1024; i += 128) {
        int arr = i >> 9, t = i & 511, r = t >> 3, sg = t & 7;
        const uint32_t* src = (arr ? g_qbl : g_qbh) + (roff + t0 + r) * 32 + sg * 4;
        CP16(sb + (arr ? OQBL : OQBH) + (uint32_t)(r * 36 + sg * 4) * 4,
             (const char*)src);
    }
    issue_kv(0, 0);

    const uint32_t* Qbh = (const uint32_t*)(sma + OQBH);
    const uint32_t* Qbl = (const uint32_t*)(sma + OQBL);
    float* Pme = (float*)(sma + OP + (uint32_t)warp * PWSZ);

    // Wait for prologue group (Q + stage 0), then hoist loop-invariant Q frags.
    CP_WAIT0();
    __syncthreads();
    uint32_t qh[4][4], ql[4][4];
#pragma unroll
    for (int kt = 0; kt < 4; kt++) {
        const int ra = (wb + g) * 36 + kt * 8 + c;
        const int rb = (wb + g + 8) * 36 + kt * 8 + c;
        qh[kt][0] = Qbh[ra]; qh[kt][1] = Qbh[rb];
        qh[kt][2] = Qbh[ra + 4]; qh[kt][3] = Qbh[rb + 4];
        ql[kt][0] = Qbl[ra]; ql[kt][1] = Qbl[rb];
        ql[kt][2] = Qbl[ra + 4]; ql[kt][3] = Qbl[rb + 4];
    }

    float rm[2] = {-CUDART_INF_F, -CUDART_INF_F};
    float rl[2] = {0.f, 0.f};
    float o[8][4];
#pragma unroll
    for (int nt = 0; nt < 8; nt++)
#pragma unroll
        for (int i = 0; i < 4; i++) o[nt][i] = 0.f;

    const int jmax = mask ? jq : 31;
    for (int j = 0; j <= jmax; j++) {
        const int st = j & 1;
        if (j + 1 <= jmax) { issue_kv(j + 1, st ^ 1); CP_WAIT1(); } else { CP_WAIT0(); }
        __syncthreads();

        const uint32_t* Kbh = (const uint32_t*)(sma + OKBH + (size_t)st * 9216);
        const uint32_t* Kbl = (const uint32_t*)(sma + OKBL + (size_t)st * 9216);
        const float*    Vst = (const float*)(sma + OV + (size_t)st * 18432);
        const int s0 = j * 64;

        // ---- S = Q K^T (3-term bf16, 3 passes, same-acc distance = 8)
        float sacc[8][4];
#pragma unroll
        for (int nt = 0; nt < 8; nt++)
#pragma unroll
            for (int i = 0; i < 4; i++) sacc[nt][i] = 0.f;

        // pass 1: Qhi x Khi
#pragma unroll
        for (int kt = 0; kt < 4; kt++)
#pragma unroll
            for (int nt = 0; nt < 8; nt++) {
                const int br = (nt * 8 + g) * 36 + kt * 8 + c;
                mma16b(sacc[nt], qh[kt][0], qh[kt][1], qh[kt][2], qh[kt][3],
                       Kbh[br], Kbh[br + 4]);
            }
        // pass 2: Qlo x Khi
#pragma unroll
        for (int kt = 0; kt < 4; kt++)
#pragma unroll
            for (int nt = 0; nt < 8; nt++) {
                const int br = (nt * 8 + g) * 36 + kt * 8 + c;
                mma16b(sacc[nt], ql[kt][0], ql[kt][1], ql[kt][2], ql[kt][3],
                       Kbh[br], Kbh[br + 4]);
            }
        // pass 3: Qhi x Klo
#pragma unroll
        for (int kt = 0; kt < 4; kt++)
#pragma unroll
            for (int nt = 0; nt < 8; nt++) {
                const int br = (nt * 8 + g) * 36 + kt * 8 + c;
                mma16b(sacc[nt], qh[kt][0], qh[kt][1], qh[kt][2], qh[kt][3],
                       Kbl[br], Kbl[br + 4]);
            }

        // ---- scale, mask
        const bool diag = (mask != 0) && (j == jq);
#pragma unroll
        for (int nt = 0; nt < 8; nt++) {
#pragma unroll
            for (int e = 0; e < 4; e++) {
                const int sg = s0 + nt * 8 + 2 * c + (e & 1);
                const int tg = t0 + wb + g + (e >> 1) * 8;
                float v = sacc[nt][e] * 8.0f;
                if (diag && sg > tg) v = -CUDART_INF_F;
                sacc[nt][e] = v;
            }
        }

        // ---- online softmax (rows g and g+8; quad reduce over c)
        float alpha[2];
#pragma unroll
        for (int i = 0; i < 2; i++) {
            float m = -CUDART_INF_F;
#pragma unroll
            for (int nt = 0; nt < 8; nt++)
                m = fmaxf(m, fmaxf(sacc[nt][2 * i], sacc[nt][2 * i + 1]));
            m = fmaxf(m, __shfl_xor_sync(0xffffffffu, m, 1));
            m = fmaxf(m, __shfl_xor_sync(0xffffffffu, m, 2));
            const float mnew = fmaxf(rm[i], m);
            alpha[i] = __expf(rm[i] - mnew);
            float s = 0.f;
#pragma unroll
            for (int nt = 0; nt < 8; nt++) {
                float p0 = __expf(sacc[nt][2 * i]     - mnew);
                float p1 = __expf(sacc[nt][2 * i + 1] - mnew);
                sacc[nt][2 * i] = p0; sacc[nt][2 * i + 1] = p1;
                s += p0 + p1;
            }
            s += __shfl_xor_sync(0xffffffffu, s, 1);
            s += __shfl_xor_sync(0xffffffffu, s, 2);
            rl[i] = rl[i] * alpha[i] + s;
            rm[i] = mnew;
        }

        // ---- scale O, stage P (tf32) warp-private (stride 68)
#pragma unroll
        for (int nt = 0; nt < 8; nt++) {
            o[nt][0] *= alpha[0]; o[nt][1] *= alpha[0];
            o[nt][2] *= alpha[1]; o[nt][3] *= alpha[1];
            *(float2*)&Pme[g * 68 + nt * 8 + 2 * c] =
                make_float2(tf32r(sacc[nt][0]), tf32r(sacc[nt][1]));
            *(float2*)&Pme[(g + 8) * 68 + nt * 8 + 2 * c] =
                make_float2(tf32r(sacc[nt][2]), tf32r(sacc[nt][3]));
        }
        __syncwarp();

        // ---- O += P V (single tf32, k8; acc distance = 8 already)
#pragma unroll
        for (int kt = 0; kt < 8; kt++) {
            const int ka = kt * 8 + c;
            uint32_t a0 = fu(Pme[g * 68 + ka]);
            uint32_t a1 = fu(Pme[(g + 8) * 68 + ka]);
            uint32_t a2 = fu(Pme[g * 68 + ka + 4]);
            uint32_t a3 = fu(Pme[(g + 8) * 68 + ka + 4]);
#pragma unroll
            for (int nt = 0; nt < 8; nt++) {
                uint32_t b0 = fu(Vst[ka * 72 + nt * 8 + g]);
                uint32_t b1 = fu(Vst[(ka + 4) * 72 + nt * 8 + g]);
                mma8(o[nt], a0, a1, a2, a3, b0, b1);
            }
        }
        __syncthreads();
    }

    // ---- normalize, write out
    const float inv0 = 1.0f / rl[0], inv1 = 1.0f / rl[1];
    const size_t r0 = roff + t0 + wb + g;
#pragma unroll
    for (int nt = 0; nt < 8; nt++) {
        *(float2*)&out[r0 * H_ + nt * 8 + 2 * c] =
            make_float2(o[nt][0] * inv0, o[nt][1] * inv0);
        *(float2*)&out[(r0 + 8) * H_ + nt * 8 + 2 * c] =
            make_float2(o[nt][2] * inv1, o[nt][3] * inv1);
    }
}

// ---------------------------------------------------------------------------
extern "C" void kernel_launch(void* const* d_in, const int* in_sizes, int n_in,
                              void* d_out, int out_size)
{
    const float* x  = (const float*)d_in[0];
    const float* Wq = (const float*)d_in[1];
    const float* Wk = (const float*)d_in[2];
    const float* Wv = (const float*)d_in[3];
    const int* should_mask = (const int*)d_in[4];
    float* out = (float*)d_out;

    cudaFuncSetAttribute(qkv_kernel,
                         cudaFuncAttributeMaxDynamicSharedMemorySize, QKV_SMEM);
    cudaFuncSetAttribute(attn_kernel,
                         cudaFuncAttributeMaxDynamicSharedMemorySize, ATT_SMEM);

    prep_kernel<<<dim3(64, 3), 256>>>(Wq, Wk, Wv);
    qkv_kernel<<<256, 384, QKV_SMEM>>>(x);
    attn_kernel<<<256, 128, ATT_SMEM>>>(out, should_mask);
}

// round 9
// speedup vs baseline: 1.5598x; 1.1293x over previous
#include <cuda_runtime.h>
#include <math.h>
#include <math_constants.h>
#include <cstdint>

// Problem shape (fixed by the reference)
constexpr int B_ = 8;
constexpr int T_ = 2048;
constexpr int E_ = 1024;
constexpr int H_ = 64;
constexpr int MT = B_ * T_;   // 16384 rows

// ---------------------------------------------------------------------------
// Device globals (no allocs allowed)
// Packed bf16 hi/lo weights + q/k activations; V transposed packed fp16.
// Word w of a packed row holds element-pairs (2w, 2w+1): low half = 2w.
// ---------------------------------------------------------------------------
__device__ __align__(16) uint32_t g_wqh[64 * 512];
__device__ __align__(16) uint32_t g_wql[64 * 512];
__device__ __align__(16) uint32_t g_wkh[64 * 512];
__device__ __align__(16) uint32_t g_wkl[64 * 512];
__device__ __align__(16) float    g_wv [64 * 1024];   // tf32-rounded

__device__ __align__(16) uint32_t g_qbh[MT * 32];
__device__ __align__(16) uint32_t g_qbl[MT * 32];
__device__ __align__(16) uint32_t g_kbh[MT * 32];
__device__ __align__(16) uint32_t g_kbl[MT * 32];
// V^T, fp16 packed along keys: g_vt[(b*64 + h)*1024 + w] = v[b][2w..2w+1][h]
__device__ __align__(16) uint32_t g_vt [B_ * 64 * 1024];

// ===========================================================================
// Baseline-PTX helpers (all valid at compute_103)
// ===========================================================================
__device__ __forceinline__ uint32_t smem_u32(const void* p) {
    uint32_t a;
    asm("{ .reg .u64 t; cvta.to.shared.u64 t, %1; cvt.u32.u64 %0, t; }"
        : "=r"(a) : "l"(p));
    return a;
}
__device__ __forceinline__ float tf32r(float v) {
    uint32_t u;
    asm("cvt.rna.tf32.f32 %0, %1;" : "=r"(u) : "f"(v));
    return __uint_as_float(u);
}
// Pack float2 -> bf16x2 hi word + bf16x2 lo word (hi = rn(v), lo = rn(v-hi))
__device__ __forceinline__ void bsplit2(float2 f, uint32_t& h, uint32_t& l) {
    asm("cvt.rn.bf16x2.f32 %0, %1, %2;" : "=r"(h) : "f"(f.y), "f"(f.x));
    float hx = __uint_as_float(h << 16);
    float hy = __uint_as_float(h & 0xffff0000u);
    asm("cvt.rn.bf16x2.f32 %0, %1, %2;" : "=r"(l) : "f"(f.y - hy), "f"(f.x - hx));
}
// Pack (hi, lo) floats -> fp16x2 word (low half = lo)
__device__ __forceinline__ uint32_t f16x2(float hi, float lo) {
    uint32_t r;
    asm("cvt.rn.f16x2.f32 %0, %1, %2;" : "=r"(r) : "f"(hi), "f"(lo));
    return r;
}
// D += A(16x16) * B(16x8), bf16 inputs, fp32 accum
__device__ __forceinline__ void mma16b(float* c,
                                       uint32_t a0, uint32_t a1, uint32_t a2, uint32_t a3,
                                       uint32_t b0, uint32_t b1) {
    asm volatile(
        "mma.sync.aligned.m16n8k16.row.col.f32.bf16.bf16.f32 "
        "{%0,%1,%2,%3}, {%4,%5,%6,%7}, {%8,%9}, {%0,%1,%2,%3};"
        : "+f"(c[0]), "+f"(c[1]), "+f"(c[2]), "+f"(c[3])
        : "r"(a0), "r"(a1), "r"(a2), "r"(a3), "r"(b0), "r"(b1));
}
// D += A(16x16) * B(16x8), fp16 inputs, fp32 accum
__device__ __forceinline__ void mma16f(float* c,
                                       uint32_t a0, uint32_t a1, uint32_t a2, uint32_t a3,
                                       uint32_t b0, uint32_t b1) {
    asm volatile(
        "mma.sync.aligned.m16n8k16.row.col.f32.f16.f16.f32 "
        "{%0,%1,%2,%3}, {%4,%5,%6,%7}, {%8,%9}, {%0,%1,%2,%3};"
        : "+f"(c[0]), "+f"(c[1]), "+f"(c[2]), "+f"(c[3])
        : "r"(a0), "r"(a1), "r"(a2), "r"(a3), "r"(b0), "r"(b1));
}
// D += A(16x8) * B(8x8), tf32 inputs, fp32 accum
__device__ __forceinline__ void mma8(float* c,
                                     uint32_t a0, uint32_t a1, uint32_t a2, uint32_t a3,
                                     uint32_t b0, uint32_t b1) {
    asm volatile(
        "mma.sync.aligned.m16n8k8.row.col.f32.tf32.tf32.f32 "
        "{%0,%1,%2,%3}, {%4,%5,%6,%7}, {%8,%9}, {%0,%1,%2,%3};"
        : "+f"(c[0]), "+f"(c[1]), "+f"(c[2]), "+f"(c[3])
        : "r"(a0), "r"(a1), "r"(a2), "r"(a3), "r"(b0), "r"(b1));
}
__device__ __forceinline__ uint32_t fu(float v) { return __float_as_uint(v); }

#define CP16(d, s)  asm volatile("cp.async.ca.shared.global [%0], [%1], 16;" :: "r"(d), "l"(s))
#define CP_COMMIT() asm volatile("cp.async.commit_group;" ::: "memory")
#define CP_WAIT0()  asm volatile("cp.async.wait_group 0;" ::: "memory")
#define CP_WAIT1()  asm volatile("cp.async.wait_group 1;" ::: "memory")

// ===========================================================================
// Kernel 0: weight prep. Wq/Wk -> packed bf16 hi/lo; Wv -> tf32-rounded.
// ===========================================================================
__global__ void prep_kernel(const float* __restrict__ Wq,
                            const float* __restrict__ Wk,
                            const float* __restrict__ Wv)
{
    const int r = blockIdx.x, mat = blockIdx.y, tid = threadIdx.x;
    if (mat < 2) {
        const float* W = mat ? Wk : Wq;
        uint32_t* dh = mat ? g_wkh : g_wqh;
        uint32_t* dl = mat ? g_wkl : g_wql;
        for (int w = tid; w < 512; w += 256) {
            float2 f = *reinterpret_cast<const float2*>(&W[r * 1024 + 2 * w]);
            uint32_t h, l; bsplit2(f, h, l);
            dh[r * 512 + w] = h; dl[r * 512 + w] = l;
        }
    } else {
        for (int i = tid; i < 1024; i += 256)
            g_wv[r * 1024 + i] = tf32r(Wv[r * 1024 + i]);
    }
}

// ===========================================================================
// Kernel 1: merged QKV projection.
// grid 256 (64 rows each), 384 threads = 12 warps: warps 0-3 Q, 4-7 K, 8-11 V.
// Q/K: 3-term bf16 m16n8k16 (term-passes). V: 1-term tf32 m16n8k8.
// Epilogue: q/k packed bf16 hi/lo; v transposed through smem -> g_vt (fp16).
// ===========================================================================
constexpr int XSTR = 40;   // floats; raw A tile rows
constexpr int WSTR = 20;   // u32;    packed B-frag banks (4g+c) conflict-free
constexpr int VSTR = 36;   // floats; tf32 B-frag banks (4g+c) conflict-free
constexpr uint32_t OX   = 0;
constexpr uint32_t OWH0 = 10240;
constexpr uint32_t OWL0 = 15360;
constexpr uint32_t OWH1 = 20480;
constexpr uint32_t OWL1 = 25600;
constexpr uint32_t OWV  = 30720;
constexpr uint32_t QSTG = 39936;
constexpr uint32_t QKV_SMEM = 2 * QSTG;   // 79872 bytes

__global__ __launch_bounds__(384) void qkv_kernel(const float* __restrict__ x)
{
    extern __shared__ char sm8[];
    const uint32_t sb = smem_u32(sm8);
    const int tid  = threadIdx.x;
    const int wid  = tid >> 5, lane = tid & 31;
    const int g = lane >> 2, c = lane & 3;
    const int mat = wid >> 2;          // 0=Q, 1=K, 2=V
    const int wb  = (wid & 3) * 16;
    const int m0  = blockIdx.x * 64;

    auto issue = [&](int ch, int st) {
        const uint32_t s0 = sb + (uint32_t)st * QSTG;
        const int k0 = ch * 32;
        for (int i = tid; i < 2048; i += 384) {
            if (i < 512) {
                int r = i >> 3, sg = i & 7;
                CP16(s0 + OX + (uint32_t)(r * XSTR + sg * 4) * 4,
                     (const char*)(x + (size_t)(m0 + r) * E_ + k0 + sg * 4));
            } else if (i < 1536) {
                int t = i - 512, arr = t >> 8, u = t & 255;
                int r = u >> 2, sg = u & 3;
                const uint32_t* src =
                    (arr == 0 ? g_wqh : arr == 1 ? g_wql : arr == 2 ? g_wkh : g_wkl)
                    + r * 512 + ch * 16 + sg * 4;
                uint32_t off = (arr == 0 ? OWH0 : arr == 1 ? OWL0 : arr == 2 ? OWH1 : OWL1);
                CP16(s0 + off + (uint32_t)(r * WSTR + sg * 4) * 4, (const char*)src);
            } else {
                int t = i - 1536, r = t >> 3, sg = t & 7;
                CP16(s0 + OWV + (uint32_t)(r * VSTR + sg * 4) * 4,
                     (const char*)(g_wv + r * 1024 + k0 + sg * 4));
            }
        }
        CP_COMMIT();
    };

    float acc[8][4];
#pragma unroll
    for (int nt = 0; nt < 8; nt++)
#pragma unroll
        for (int i = 0; i < 4; i++) acc[nt][i] = 0.f;

    issue(0, 0);

    for (int ch = 0; ch < 32; ch++) {
        const int st = ch & 1;
        if (ch + 1 < 32) { issue(ch + 1, st ^ 1); CP_WAIT1(); } else { CP_WAIT0(); }
        __syncthreads();

        const char* stage = sm8 + (size_t)st * QSTG;
        const float* Xf = (const float*)(stage + OX);

        if (mat < 2) {
            const uint32_t* WH = (const uint32_t*)(stage + (mat ? OWH1 : OWH0));
            const uint32_t* WL = (const uint32_t*)(stage + (mat ? OWL1 : OWL0));
            uint32_t ah[2][4], al[2][4];
#pragma unroll
            for (int kt = 0; kt < 2; kt++) {
                const int cb = kt * 16 + 2 * c;
                float2 f00 = *(const float2*)&Xf[(wb + g) * XSTR + cb];
                float2 f10 = *(const float2*)&Xf[(wb + g + 8) * XSTR + cb];
                float2 f01 = *(const float2*)&Xf[(wb + g) * XSTR + cb + 8];
                float2 f11 = *(const float2*)&Xf[(wb + g + 8) * XSTR + cb + 8];
                bsplit2(f00, ah[kt][0], al[kt][0]);
                bsplit2(f10, ah[kt][1], al[kt][1]);
                bsplit2(f01, ah[kt][2], al[kt][2]);
                bsplit2(f11, ah[kt][3], al[kt][3]);
            }
#pragma unroll
            for (int kt = 0; kt < 2; kt++)
#pragma unroll
                for (int nt = 0; nt < 8; nt++) {
                    const int br = (nt * 8 + g) * WSTR + kt * 8 + c;
                    mma16b(acc[nt], ah[kt][0], ah[kt][1], ah[kt][2], ah[kt][3],
                           WH[br], WH[br + 4]);
                }
#pragma unroll
            for (int kt = 0; kt < 2; kt++)
#pragma unroll
                for (int nt = 0; nt < 8; nt++) {
                    const int br = (nt * 8 + g) * WSTR + kt * 8 + c;
                    mma16b(acc[nt], al[kt][0], al[kt][1], al[kt][2], al[kt][3],
                           WH[br], WH[br + 4]);
                }
#pragma unroll
            for (int kt = 0; kt < 2; kt++)
#pragma unroll
                for (int nt = 0; nt < 8; nt++) {
                    const int br = (nt * 8 + g) * WSTR + kt * 8 + c;
                    mma16b(acc[nt], ah[kt][0], ah[kt][1], ah[kt][2], ah[kt][3],
                           WL[br], WL[br + 4]);
                }
        } else {
            const float* WV = (const float*)(stage + OWV);
#pragma unroll
            for (int kt = 0; kt < 4; kt++) {
                const int ka = kt * 8 + c;
                uint32_t a0 = fu(tf32r(Xf[(wb + g) * XSTR + ka]));
                uint32_t a1 = fu(tf32r(Xf[(wb + g + 8) * XSTR + ka]));
                uint32_t a2 = fu(tf32r(Xf[(wb + g) * XSTR + ka + 4]));
                uint32_t a3 = fu(tf32r(Xf[(wb + g + 8) * XSTR + ka + 4]));
#pragma unroll
                for (int nt = 0; nt < 8; nt++) {
                    const int br = (nt * 8 + g) * VSTR + ka;
                    mma8(acc[nt], a0, a1, a2, a3, fu(WV[br]), fu(WV[br + 4]));
                }
            }
        }
        __syncthreads();
    }

    // ---- epilogue
    const int r0 = m0 + wb + g, r1 = r0 + 8;
    if (mat < 2) {
        uint32_t* dh = mat ? g_kbh : g_qbh;
        uint32_t* dl = mat ? g_kbl : g_qbl;
#pragma unroll
        for (int nt = 0; nt < 8; nt++) {
            const int w = nt * 4 + c;
            uint32_t h, l;
            bsplit2(make_float2(acc[nt][0], acc[nt][1]), h, l);
            dh[(size_t)r0 * 32 + w] = h; dl[(size_t)r0 * 32 + w] = l;
            bsplit2(make_float2(acc[nt][2], acc[nt][3]), h, l);
            dh[(size_t)r1 * 32 + w] = h; dl[(size_t)r1 * 32 + w] = l;
        }
    } else {
        // stage v tile (fp32) into smem for the transpose
        float* vbuf = (float*)sm8;   // [64][68]
#pragma unroll
        for (int nt = 0; nt < 8; nt++) {
            vbuf[(wb + g) * 68 + nt * 8 + 2 * c]     = acc[nt][0];
            vbuf[(wb + g) * 68 + nt * 8 + 2 * c + 1] = acc[nt][1];
            vbuf[(wb + g + 8) * 68 + nt * 8 + 2 * c]     = acc[nt][2];
            vbuf[(wb + g + 8) * 68 + nt * 8 + 2 * c + 1] = acc[nt][3];
        }
    }
    __syncthreads();
    // all threads: transposed packed-fp16 write of the V tile
    {
        const float* vbuf = (const float*)sm8;
        const int bb = m0 >> 11;             // batch
        const int kw0 = (m0 & 2047) >> 1;    // 32-word base in key dim
        for (int i = tid; i < 2048; i += 384) {
            int h = i >> 5, w = i & 31;
            float lo = vbuf[(2 * w) * 68 + h];
            float hi = vbuf[(2 * w + 1) * 68 + h];
            g_vt[(size_t)(bb * 64 + h) * 1024 + kw0 + w] = f16x2(hi, lo);
        }
    }
}

// ===========================================================================
// Kernel 2: flash attention.
// 128 threads (4 warps), 64 queries/CTA, warp = 16 query rows x 64 keys.
// QK^T: 3-term bf16 m16n8k16, Q frags hoisted.  PV: fp16 m16n8k16 —
// P fragments built in registers (no smem round-trip), V^T fp16 tiles.
// smem 72KB -> 3 CTAs/SM.
// ===========================================================================
constexpr uint32_t OQBH = 0;
constexpr uint32_t OQBL = 9216;
constexpr uint32_t OKBH = 18432;   // + st*9216  (stages 18432, 27648)
constexpr uint32_t OKBL = 36864;   // + st*9216  (stages 36864, 46080)
constexpr uint32_t OV   = 55296;   // + st*9216  (stages 55296, 64512)
constexpr uint32_t ATT_SMEM = 73728;

__global__ __launch_bounds__(128, 3) void attn_kernel(
    float* __restrict__ out, const int* __restrict__ maskp)
{
    extern __shared__ char sma[];
    const uint32_t sb = smem_u32(sma);
    const int tid  = threadIdx.x;
    const int warp = tid >> 5, lane = tid & 31;
    const int g = lane >> 2, c = lane & 3;
    const int wb = warp * 16;

    // ---- balanced (jq, b) schedule
    const int bid = blockIdx.x;
    int jq, b;
    if (bid >= 148) {
        int p = bid - 148;
        if (p < 104) { jq = 26 - (p % 13); b = p / 13; }
        else         { jq = 13;            b = (p - 104) * 2 + 1; }
    } else if (bid >= 108) {
        int s = bid - 108;
        if (s < 32) { jq = 28 + (s >> 3); b = s & 7; }
        else        { jq = 27;            b = s - 32; }
    } else {
        if (bid < 104) { jq = bid % 13; b = bid / 13; }
        else           { jq = 13;       b = (bid - 104) * 2; }
    }
    const int t0   = jq * 64;
    const int mask = *maskp;
    const size_t roff = (size_t)b * T_;

    auto issue_kv = [&](int j, int st) {
        const int s0r = j * 64;
        const uint32_t kb = sb + OKBH + (uint32_t)st * 9216;
        const uint32_t kl = sb + OKBL + (uint32_t)st * 9216;
        const uint32_t vv = sb + OV   + (uint32_t)st * 9216;
        for (int i = tid; i < 1536; i += 128) {
            if (i < 512) {
                int r = i >> 3, sg = i & 7;
                CP16(kb + (uint32_t)(r * 36 + sg * 4) * 4,
                     (const char*)(g_kbh + (roff + s0r + r) * 32 + sg * 4));
            } else if (i < 1024) {
                int t = i - 512, r = t >> 3, sg = t & 7;
                CP16(kl + (uint32_t)(r * 36 + sg * 4) * 4,
                     (const char*)(g_kbl + (roff + s0r + r) * 32 + sg * 4));
            } else {
                int t = i - 1024, h = t >> 3, sg = t & 7;
                CP16(vv + (uint32_t)(h * 36 + sg * 4) * 4,
                     (const char*)(g_vt + (size_t)(b * 64 + h) * 1024
                                   + (s0r >> 1) + sg * 4));
            }
        }
        CP_COMMIT();
    };

    // ---- prologue: Q (packed) + first K/V stage
    for (int i = tid; i < 1024; i += 128) {
        int arr = i >> 9, t = i & 511, r = t >> 3, sg = t & 7;
        const uint32_t* src = (arr ? g_qbl : g_qbh) + (roff + t0 + r) * 32 + sg * 4;
        CP16(sb + (arr ? OQBL : OQBH) + (uint32_t)(r * 36 + sg * 4) * 4,
             (const char*)src);
    }
    issue_kv(0, 0);

    const uint32_t* Qbh = (const uint32_t*)(sma + OQBH);
    const uint32_t* Qbl = (const uint32_t*)(sma + OQBL);

    CP_WAIT0();
    __syncthreads();
    uint32_t qh[4][4], ql[4][4];
#pragma unroll
    for (int kt = 0; kt < 4; kt++) {
        const int ra = (wb + g) * 36 + kt * 8 + c;
        const int rb = (wb + g + 8) * 36 + kt * 8 + c;
        qh[kt][0] = Qbh[ra]; qh[kt][1] = Qbh[rb];
        qh[kt][2] = Qbh[ra + 4]; qh[kt][3] = Qbh[rb + 4];
        ql[kt][0] = Qbl[ra]; ql[kt][1] = Qbl[rb];
        ql[kt][2] = Qbl[ra + 4]; ql[kt][3] = Qbl[rb + 4];
    }

    float rm[2] = {-CUDART_INF_F, -CUDART_INF_F};
    float rl[2] = {0.f, 0.f};
    float o[8][4];
#pragma unroll
    for (int nt = 0; nt < 8; nt++)
#pragma unroll
        for (int i = 0; i < 4; i++) o[nt][i] = 0.f;

    const int jmax = mask ? jq : 31;
    for (int j = 0; j <= jmax; j++) {
        const int st = j & 1;
        if (j + 1 <= jmax) { issue_kv(j + 1, st ^ 1); CP_WAIT1(); } else { CP_WAIT0(); }
        __syncthreads();

        const uint32_t* Kbh = (const uint32_t*)(sma + OKBH + (size_t)st * 9216);
        const uint32_t* Kbl = (const uint32_t*)(sma + OKBL + (size_t)st * 9216);
        const uint32_t* Vt  = (const uint32_t*)(sma + OV   + (size_t)st * 9216);
        const int s0 = j * 64;

        // ---- S = Q K^T (3-term bf16, 3 passes)
        float sacc[8][4];
#pragma unroll
        for (int nt = 0; nt < 8; nt++)
#pragma unroll
            for (int i = 0; i < 4; i++) sacc[nt][i] = 0.f;

#pragma unroll
        for (int kt = 0; kt < 4; kt++)
#pragma unroll
            for (int nt = 0; nt < 8; nt++) {
                const int br = (nt * 8 + g) * 36 + kt * 8 + c;
                mma16b(sacc[nt], qh[kt][0], qh[kt][1], qh[kt][2], qh[kt][3],
                       Kbh[br], Kbh[br + 4]);
            }
#pragma unroll
        for (int kt = 0; kt < 4; kt++)
#pragma unroll
            for (int nt = 0; nt < 8; nt++) {
                const int br = (nt * 8 + g) * 36 + kt * 8 + c;
                mma16b(sacc[nt], ql[kt][0], ql[kt][1], ql[kt][2], ql[kt][3],
                       Kbh[br], Kbh[br + 4]);
            }
#pragma unroll
        for (int kt = 0; kt < 4; kt++)
#pragma unroll
            for (int nt = 0; nt < 8; nt++) {
                const int br = (nt * 8 + g) * 36 + kt * 8 + c;
                mma16b(sacc[nt], qh[kt][0], qh[kt][1], qh[kt][2], qh[kt][3],
                       Kbl[br], Kbl[br + 4]);
            }

        // ---- scale, mask
        const bool diag = (mask != 0) && (j == jq);
#pragma unroll
        for (int nt = 0; nt < 8; nt++) {
#pragma unroll
            for (int e = 0; e < 4; e++) {
                const int sg = s0 + nt * 8 + 2 * c + (e & 1);
                const int tg = t0 + wb + g + (e >> 1) * 8;
                float v = sacc[nt][e] * 8.0f;
                if (diag && sg > tg) v = -CUDART_INF_F;
                sacc[nt][e] = v;
            }
        }

        // ---- online softmax (rows g and g+8; quad reduce over c)
        float alpha[2];
#pragma unroll
        for (int i = 0; i < 2; i++) {
            float m = -CUDART_INF_F;
#pragma unroll
            for (int nt = 0; nt < 8; nt++)
                m = fmaxf(m, fmaxf(sacc[nt][2 * i], sacc[nt][2 * i + 1]));
            m = fmaxf(m, __shfl_xor_sync(0xffffffffu, m, 1));
            m = fmaxf(m, __shfl_xor_sync(0xffffffffu, m, 2));
            const float mnew = fmaxf(rm[i], m);
            alpha[i] = __expf(rm[i] - mnew);
            float s = 0.f;
#pragma unroll
            for (int nt = 0; nt < 8; nt++) {
                float p0 = __expf(sacc[nt][2 * i]     - mnew);
                float p1 = __expf(sacc[nt][2 * i + 1] - mnew);
                sacc[nt][2 * i] = p0; sacc[nt][2 * i + 1] = p1;
                s += p0 + p1;
            }
            s += __shfl_xor_sync(0xffffffffu, s, 1);
            s += __shfl_xor_sync(0xffffffffu, s, 2);
            rl[i] = rl[i] * alpha[i] + s;
            rm[i] = mnew;
        }

        // ---- scale O; O += P V (fp16, P frags direct from registers)
#pragma unroll
        for (int nt = 0; nt < 8; nt++) {
            o[nt][0] *= alpha[0]; o[nt][1] *= alpha[0];
            o[nt][2] *= alpha[1]; o[nt][3] *= alpha[1];
        }
#pragma unroll
        for (int kt = 0; kt < 4; kt++) {
            // A-frag rows g/g+8, k = 16kt + {2c,2c+1} and +8
            uint32_t a0 = f16x2(sacc[2 * kt][1],     sacc[2 * kt][0]);
            uint32_t a1 = f16x2(sacc[2 * kt][3],     sacc[2 * kt][2]);
            uint32_t a2 = f16x2(sacc[2 * kt + 1][1], sacc[2 * kt + 1][0]);
            uint32_t a3 = f16x2(sacc[2 * kt + 1][3], sacc[2 * kt + 1][2]);
#pragma unroll
            for (int nt = 0; nt < 8; nt++) {
                const int br = (nt * 8 + g) * 36 + kt * 8 + c;
                mma16f(o[nt], a0, a1, a2, a3, Vt[br], Vt[br + 4]);
            }
        }
        __syncthreads();
    }

    // ---- normalize, write out
    const float inv0 = 1.0f / rl[0], inv1 = 1.0f / rl[1];
    const size_t r0 = roff + t0 + wb + g;
#pragma unroll
    for (int nt = 0; nt < 8; nt++) {
        *(float2*)&out[r0 * H_ + nt * 8 + 2 * c] =
            make_float2(o[nt][0] * inv0, o[nt][1] * inv0);
        *(float2*)&out[(r0 + 8) * H_ + nt * 8 + 2 * c] =
            make_float2(o[nt][2] * inv1, o[nt][3] * inv1);
    }
}

// ---------------------------------------------------------------------------
extern "C" void kernel_launch(void* const* d_in, const int* in_sizes, int n_in,
                              void* d_out, int out_size)
{
    const float* x  = (const float*)d_in[0];
    const float* Wq = (const float*)d_in[1];
    const float* Wk = (const float*)d_in[2];
    const float* Wv = (const float*)d_in[3];
    const int* should_mask = (const int*)d_in[4];
    float* out = (float*)d_out;

    cudaFuncSetAttribute(qkv_kernel,
                         cudaFuncAttributeMaxDynamicSharedMemorySize, QKV_SMEM);
    cudaFuncSetAttribute(attn_kernel,
                         cudaFuncAttributeMaxDynamicSharedMemorySize, ATT_SMEM);

    prep_kernel<<<dim3(64, 3), 256>>>(Wq, Wk, Wv);
    qkv_kernel<<<256, 384, QKV_SMEM>>>(x);
    attn_kernel<<<256, 128, ATT_SMEM>>>(out, should_mask);
}